// round 1
// baseline (speedup 1.0000x reference)
#include <cuda_runtime.h>
#include <math.h>

#define NB 4
#define NS 2048
#define NE 1024
#define ND 128

// Scratch (device globals: allocation-free per harness rules)
__device__ float g_q[NB * NS * ND];
__device__ float g_k[NB * NS * ND];
__device__ float g_v[NB * NS * ND];
__device__ float g_s[(size_t)NB * NS * NS];   // 64 MB score/prob matrix

// ---------------------------------------------------------------------------
// Kernel 1: fused QKV projection.  [8192,1024] x [1024,128] + bias, x3
// BM=64, BN=128, BK=8, 256 threads, 8x4 microtile per thread.
// blockIdx.y selects q/k/v.
// ---------------------------------------------------------------------------
__global__ __launch_bounds__(256) void qkv_kernel(
    const float* __restrict__ x,
    const float* __restrict__ wq, const float* __restrict__ bq,
    const float* __restrict__ wk, const float* __restrict__ bk,
    const float* __restrict__ wv, const float* __restrict__ bv)
{
    const float *w, *bias;
    float *outp;
    if (blockIdx.y == 0)      { w = wq; bias = bq; outp = g_q; }
    else if (blockIdx.y == 1) { w = wk; bias = bk; outp = g_k; }
    else                      { w = wv; bias = bv; outp = g_v; }

    __shared__ __align__(16) float As[8][64];
    __shared__ __align__(16) float Bs[8][128];

    const int tid  = threadIdx.x;
    const int m0   = blockIdx.x * 64;
    const int tr   = tid >> 5;          // 0..7  : row group (warp-uniform)
    const int tc   = tid & 31;          // 0..31 : col group
    const int arow = tid >> 2;          // 0..63
    const int acol = (tid & 3) * 2;     // 0,2,4,6
    const int brow = tid >> 5;          // 0..7
    const int bcol = (tid & 31) * 4;    // 0..124

    float acc[8][4];
    #pragma unroll
    for (int i = 0; i < 8; i++)
        #pragma unroll
        for (int j = 0; j < 4; j++) acc[i][j] = 0.f;

    for (int k0 = 0; k0 < NE; k0 += 8) {
        float2 a2 = *(const float2*)(x + (size_t)(m0 + arow) * NE + k0 + acol);
        float4 b4 = *(const float4*)(w + (size_t)(k0 + brow) * ND + bcol);
        __syncthreads();
        As[acol    ][arow] = a2.x;
        As[acol + 1][arow] = a2.y;
        *(float4*)&Bs[brow][bcol] = b4;
        __syncthreads();
        #pragma unroll
        for (int k = 0; k < 8; k++) {
            float a[8];
            #pragma unroll
            for (int i = 0; i < 8; i++) a[i] = As[k][tr * 8 + i];  // warp-broadcast
            float4 bb = *(const float4*)&Bs[k][tc * 4];
            #pragma unroll
            for (int i = 0; i < 8; i++) {
                acc[i][0] = fmaf(a[i], bb.x, acc[i][0]);
                acc[i][1] = fmaf(a[i], bb.y, acc[i][1]);
                acc[i][2] = fmaf(a[i], bb.z, acc[i][2]);
                acc[i][3] = fmaf(a[i], bb.w, acc[i][3]);
            }
        }
    }

    float4 bia = *(const float4*)(bias + tc * 4);
    #pragma unroll
    for (int i = 0; i < 8; i++) {
        float4 r;
        r.x = acc[i][0] + bia.x;
        r.y = acc[i][1] + bia.y;
        r.z = acc[i][2] + bia.z;
        r.w = acc[i][3] + bia.w;
        *(float4*)(outp + (size_t)(m0 + tr * 8 + i) * ND + tc * 4) = r;
    }
}

// Triangular block decode: bidx in [0, 136) -> (bi, bj), bj <= bi, bi in [0,16)
__device__ __forceinline__ void tri_decode(int bidx, int& bi, int& bj)
{
    int r = (int)((sqrtf(8.f * bidx + 1.f) - 1.f) * 0.5f);
    while ((r + 1) * (r + 2) / 2 <= bidx) r++;
    while (r * (r + 1) / 2 > bidx) r--;
    bi = r;
    bj = bidx - r * (r + 1) / 2;
}

// ---------------------------------------------------------------------------
// Kernel 2: scores = (q . k^T) * scale, causal mask -> -inf.
// Lower-triangular 128x128 tiles only. 136 blocks x 4 batches.
// GEMM M=128 N=128 K=128, 256 threads, 8x8 microtile.
// ---------------------------------------------------------------------------
__global__ __launch_bounds__(256) void scores_kernel()
{
    int bi, bj;
    tri_decode(blockIdx.x, bi, bj);
    const int b  = blockIdx.y;
    const int i0 = bi * 128;
    const int j0 = bj * 128;

    const float* q  = g_q + (size_t)b * NS * ND;
    const float* km = g_k + (size_t)b * NS * ND;
    float* sout     = g_s + ((size_t)b << 22);

    __shared__ __align__(16) float As[8][128];
    __shared__ __align__(16) float Bs[8][128];

    const int tid  = threadIdx.x;
    const int row  = tid >> 1;          // 0..127
    const int half = tid & 1;
    const int tr   = tid >> 4;          // 0..15
    const int tc   = tid & 15;          // 0..15

    float acc[8][8];
    #pragma unroll
    for (int i = 0; i < 8; i++)
        #pragma unroll
        for (int j = 0; j < 8; j++) acc[i][j] = 0.f;

    for (int k0 = 0; k0 < ND; k0 += 8) {
        float4 a4 = *(const float4*)(q  + (size_t)(i0 + row) * ND + k0 + half * 4);
        float4 b4 = *(const float4*)(km + (size_t)(j0 + row) * ND + k0 + half * 4);
        __syncthreads();
        As[half * 4    ][row] = a4.x;
        As[half * 4 + 1][row] = a4.y;
        As[half * 4 + 2][row] = a4.z;
        As[half * 4 + 3][row] = a4.w;
        Bs[half * 4    ][row] = b4.x;
        Bs[half * 4 + 1][row] = b4.y;
        Bs[half * 4 + 2][row] = b4.z;
        Bs[half * 4 + 3][row] = b4.w;
        __syncthreads();
        #pragma unroll
        for (int k = 0; k < 8; k++) {
            float4 a0 = *(const float4*)&As[k][tr * 8];
            float4 a1 = *(const float4*)&As[k][tr * 8 + 4];
            float4 b0 = *(const float4*)&Bs[k][tc * 8];
            float4 b1 = *(const float4*)&Bs[k][tc * 8 + 4];
            float av[8] = {a0.x, a0.y, a0.z, a0.w, a1.x, a1.y, a1.z, a1.w};
            float bv[8] = {b0.x, b0.y, b0.z, b0.w, b1.x, b1.y, b1.z, b1.w};
            #pragma unroll
            for (int i = 0; i < 8; i++)
                #pragma unroll
                for (int j = 0; j < 8; j++)
                    acc[i][j] = fmaf(av[i], bv[j], acc[i][j]);
        }
    }

    const float scale = 0.08838834764831845f;   // 1/sqrt(128)
    #pragma unroll
    for (int i = 0; i < 8; i++) {
        const int gi = i0 + tr * 8 + i;
        #pragma unroll
        for (int j = 0; j < 8; j++) {
            const int gj = j0 + tc * 8 + j;
            sout[(size_t)gi * NS + gj] = (gj <= gi) ? acc[i][j] * scale : -INFINITY;
        }
    }
}

// ---------------------------------------------------------------------------
// Kernel 3: row softmax in place over padded length (next 128 multiple).
// Padded entries are -inf -> exp()=0 -> written as exact zeros (consumed by pv).
// ---------------------------------------------------------------------------
__global__ __launch_bounds__(256) void softmax_kernel()
{
    __shared__ float buf[2048];
    __shared__ float red[8];

    const int r   = blockIdx.x;
    const int b   = r >> 11;
    const int i   = r & 2047;
    float* s      = g_s + ((size_t)b << 22) + (size_t)i * NS;
    const int Lp  = ((i >> 7) + 1) << 7;
    const int tid = threadIdx.x;
    const int lane = tid & 31, wid = tid >> 5;

    float m = -INFINITY;
    for (int j = tid; j < Lp; j += 256) {
        float v = s[j];
        buf[j] = v;
        m = fmaxf(m, v);
    }
    #pragma unroll
    for (int o = 16; o; o >>= 1) m = fmaxf(m, __shfl_xor_sync(0xffffffffu, m, o));
    if (lane == 0) red[wid] = m;
    __syncthreads();
    m = red[0];
    #pragma unroll
    for (int w = 1; w < 8; w++) m = fmaxf(m, red[w]);
    __syncthreads();

    float sum = 0.f;
    for (int j = tid; j < Lp; j += 256) {
        float e = expf(buf[j] - m);   // exp(-inf - m) == 0 handles padding
        buf[j] = e;
        sum += e;
    }
    #pragma unroll
    for (int o = 16; o; o >>= 1) sum += __shfl_xor_sync(0xffffffffu, sum, o);
    if (lane == 0) red[wid] = sum;
    __syncthreads();
    sum = red[0];
    #pragma unroll
    for (int w = 1; w < 8; w++) sum += red[w];

    const float inv = 1.f / sum;
    for (int j = tid; j < Lp; j += 256) s[j] = buf[j] * inv;
}

// ---------------------------------------------------------------------------
// Kernel 4: out += P[128x128 tile] . V[128x128].  Triangular block pairs,
// fp32 atomicAdd accumulation into d_out (zeroed beforehand).
// ---------------------------------------------------------------------------
__global__ __launch_bounds__(256) void pv_kernel(float* __restrict__ out)
{
    int bi, bj;
    tri_decode(blockIdx.x, bi, bj);
    const int b  = blockIdx.y;
    const int i0 = bi * 128;
    const int j0 = bj * 128;

    const float* p = g_s + ((size_t)b << 22);
    const float* v = g_v + (size_t)b * NS * ND;

    __shared__ __align__(16) float As[8][128];
    __shared__ __align__(16) float Bs[8][128];

    const int tid  = threadIdx.x;
    const int row  = tid >> 1;
    const int half = tid & 1;
    const int brow = tid >> 5;          // 0..7
    const int bcol = (tid & 31) * 4;
    const int tr   = tid >> 4;
    const int tc   = tid & 15;

    float acc[8][8];
    #pragma unroll
    for (int i = 0; i < 8; i++)
        #pragma unroll
        for (int j = 0; j < 8; j++) acc[i][j] = 0.f;

    for (int k0 = 0; k0 < 128; k0 += 8) {
        float4 a4 = *(const float4*)(p + (size_t)(i0 + row) * NS + j0 + k0 + half * 4);
        float4 b4 = *(const float4*)(v + (size_t)(j0 + k0 + brow) * ND + bcol);
        __syncthreads();
        As[half * 4    ][row] = a4.x;
        As[half * 4 + 1][row] = a4.y;
        As[half * 4 + 2][row] = a4.z;
        As[half * 4 + 3][row] = a4.w;
        *(float4*)&Bs[brow][bcol] = b4;
        __syncthreads();
        #pragma unroll
        for (int k = 0; k < 8; k++) {
            float4 a0 = *(const float4*)&As[k][tr * 8];
            float4 a1 = *(const float4*)&As[k][tr * 8 + 4];
            float4 b0 = *(const float4*)&Bs[k][tc * 8];
            float4 b1 = *(const float4*)&Bs[k][tc * 8 + 4];
            float av[8] = {a0.x, a0.y, a0.z, a0.w, a1.x, a1.y, a1.z, a1.w};
            float bv[8] = {b0.x, b0.y, b0.z, b0.w, b1.x, b1.y, b1.z, b1.w};
            #pragma unroll
            for (int i = 0; i < 8; i++)
                #pragma unroll
                for (int j = 0; j < 8; j++)
                    acc[i][j] = fmaf(av[i], bv[j], acc[i][j]);
        }
    }

    #pragma unroll
    for (int i = 0; i < 8; i++) {
        const int gi = i0 + tr * 8 + i;
        float* orow = out + ((size_t)(b * NS + gi)) * ND + tc * 8;
        #pragma unroll
        for (int j = 0; j < 8; j++)
            atomicAdd(orow + j, acc[i][j]);
    }
}

// ---------------------------------------------------------------------------
extern "C" void kernel_launch(void* const* d_in, const int* in_sizes, int n_in,
                              void* d_out, int out_size)
{
    const float* x  = (const float*)d_in[0];
    const float* wq = (const float*)d_in[1];
    const float* bq = (const float*)d_in[2];
    const float* wk = (const float*)d_in[3];
    const float* bk = (const float*)d_in[4];
    const float* wv = (const float*)d_in[5];
    const float* bv = (const float*)d_in[6];
    float* out = (float*)d_out;

    cudaMemsetAsync(out, 0, (size_t)out_size * sizeof(float));
    qkv_kernel<<<dim3((NB * NS) / 64, 3), 256>>>(x, wq, bq, wk, bk, wv, bv);
    scores_kernel<<<dim3(136, NB), 256>>>();
    softmax_kernel<<<NB * NS, 256>>>();
    pv_kernel<<<dim3(136, NB), 256>>>(out);
}